// round 17
// baseline (speedup 1.0000x reference)
#include <cuda_runtime.h>

#define BB    8
#define NN    2048
#define NPTS  (BB*NN)        // 16384
#define CC    512
#define CIN   128
#define HH    96
#define WIW   96
#define IMG_ELEMS (BB*HH*WIW*CIN)   // 9437184

#define L0OFF (NPTS*CC)              // 8388608
#define L1OFF (L0OFF + NPTS*8)       // 8519680
#define L2OFF (L1OFF + NPTS*16)      // 8781824

// -------- scratch (static device allocation; no cudaMalloc allowed) --------
__device__ __align__(16) float g_TI [IMG_ELEMS];   // I  transposed to (b,x,y,c)
__device__ __align__(16) float g_TIT[IMG_ELEMS];   // IT transposed
__device__ __align__(16) float g_TJX[IMG_ELEMS];   // (IX - 0.5*I) transposed
__device__ __align__(16) float g_TJY[IMG_ELEMS];   // (IY - 0.5*I) transposed
__device__ __align__(16) float g_mask[NPTS*64];    // softmax mask, [pt][s*8+g]
__device__ __align__(16) float g_Z[NPTS*8*CIN];    // Z[pt][g][k]

#define K1_PTS 16
#define K0_BLOCKS 9216               // 12 * 96 * 8
#define K1_BLOCKS (NPTS/K1_PTS)      // 1024
#define K01_BLOCKS (K0_BLOCKS + K1_BLOCKS)  // 10240 (k1 = every 10th block)

// ============================================================================
// K01: fused transpose (k0 path) + logits/rects (k1 path), block-level dispatch.
// ============================================================================
union SmemK01 {
    struct { float tI[32][33], tIX[32][33], tIY[32][33], tIT[32][33]; } a;
    struct { float xs[K1_PTS][516]; float lg[K1_PTS][72]; float rects[K1_PTS][56]; } b;
};

__global__ void __launch_bounds__(256) k01_fused(
        const float* __restrict__ I, const float* __restrict__ IX,
        const float* __restrict__ IY, const float* __restrict__ IT,
        const float* __restrict__ x, const float* __restrict__ r,
        const float* __restrict__ Wr, const float* __restrict__ br,
        const float* __restrict__ Wm, const float* __restrict__ bm,
        float* __restrict__ out) {
    __shared__ SmemK01 sm;
    int bid = blockIdx.x;
    int rmod = bid % 10;
    int tid = threadIdx.x;

    if (rmod != 9) {
        // ---------------- k0 path: transpose with fused JX/JY ----------------
        int k0id = (bid/10)*9 + rmod;            // 0 .. 9215
        int bx = k0id % 12, by = (k0id/12) % 96, bz = k0id / (12*96);
        int ct = bx / 3, yt = bx % 3;
        int xx = by, b = bz;
        int tx = tid & 31, ty = tid >> 5;
        #pragma unroll
        for (int rr = ty; rr < 32; rr += 8) {
            int c = ct*32 + rr;
            int y = yt*32 + tx;
            int src = ((b*CIN + c)*HH + xx)*WIW + y;
            sm.a.tI [rr][tx] = I [src];
            sm.a.tIX[rr][tx] = IX[src];
            sm.a.tIY[rr][tx] = IY[src];
            sm.a.tIT[rr][tx] = IT[src];
        }
        __syncthreads();
        #pragma unroll
        for (int rr = ty; rr < 32; rr += 8) {
            int c = ct*32 + tx;
            int y = yt*32 + rr;
            int dst = ((b*HH + xx)*WIW + y)*CIN + c;
            float vi = sm.a.tI[tx][rr];
            g_TI [dst] = vi;
            g_TIT[dst] = sm.a.tIT[tx][rr];
            g_TJX[dst] = sm.a.tIX[tx][rr] - 0.5f*vi;
            g_TJY[dst] = sm.a.tIY[tx][rr] - 0.5f*vi;
        }
        return;
    }

    // ---------------- k1 path: logits + rect splits + softmax ----------------
    int p0 = (bid/10) * K1_PTS;

    for (int i = tid; i < K1_PTS*CC; i += 256) {
        int p = i >> 9, k = i & 511;
        sm.b.xs[p][k] = x[(p0+p)*CC + k];
    }
    __syncthreads();

    // mask logits: thread = (point, 4 cols); float4 loads; split-4 accumulation
    {
        int p = tid >> 4, q = tid & 15;
        float4 a0 = {0,0,0,0}, a1 = {0,0,0,0}, a2 = {0,0,0,0}, a3 = {0,0,0,0};
        #pragma unroll 4
        for (int k = 0; k < CC; k += 4) {
            float4 xv = *(const float4*)&sm.b.xs[p][k];
            float4 w0 = *(const float4*)&Wm[(k+0)*64 + q*4];
            float4 w1 = *(const float4*)&Wm[(k+1)*64 + q*4];
            float4 w2 = *(const float4*)&Wm[(k+2)*64 + q*4];
            float4 w3 = *(const float4*)&Wm[(k+3)*64 + q*4];
            a0.x += xv.x*w0.x; a0.y += xv.x*w0.y; a0.z += xv.x*w0.z; a0.w += xv.x*w0.w;
            a1.x += xv.y*w1.x; a1.y += xv.y*w1.y; a1.z += xv.y*w1.z; a1.w += xv.y*w1.w;
            a2.x += xv.z*w2.x; a2.y += xv.z*w2.y; a2.z += xv.z*w2.z; a2.w += xv.z*w2.w;
            a3.x += xv.w*w3.x; a3.y += xv.w*w3.y; a3.z += xv.w*w3.z; a3.w += xv.w*w3.w;
        }
        sm.b.lg[p][7 + q*4 + 0] = (a0.x+a1.x) + (a2.x+a3.x);
        sm.b.lg[p][7 + q*4 + 1] = (a0.y+a1.y) + (a2.y+a3.y);
        sm.b.lg[p][7 + q*4 + 2] = (a0.z+a1.z) + (a2.z+a3.z);
        sm.b.lg[p][7 + q*4 + 3] = (a0.w+a1.w) + (a2.w+a3.w);
    }

    // ratio logits: pairwise fp32 chunks of 8, summed into double
    if (tid < K1_PTS*7) {
        int p = tid / 7, j = tid % 7;
        double acc = 0.0;
        #pragma unroll 4
        for (int kb = 0; kb < CC; kb += 16) {
            const float* xp = sm.b.xs[p];
            float s0 = ((xp[kb+0]*Wr[(kb+0)*7+j] + xp[kb+1]*Wr[(kb+1)*7+j])
                      + (xp[kb+2]*Wr[(kb+2)*7+j] + xp[kb+3]*Wr[(kb+3)*7+j]))
                     + ((xp[kb+4]*Wr[(kb+4)*7+j] + xp[kb+5]*Wr[(kb+5)*7+j])
                      + (xp[kb+6]*Wr[(kb+6)*7+j] + xp[kb+7]*Wr[(kb+7)*7+j]));
            float s1 = ((xp[kb+8]*Wr[(kb+8)*7+j] + xp[kb+9]*Wr[(kb+9)*7+j])
                      + (xp[kb+10]*Wr[(kb+10)*7+j] + xp[kb+11]*Wr[(kb+11)*7+j]))
                     + ((xp[kb+12]*Wr[(kb+12)*7+j] + xp[kb+13]*Wr[(kb+13)*7+j])
                      + (xp[kb+14]*Wr[(kb+14)*7+j] + xp[kb+15]*Wr[(kb+15)*7+j]));
            acc += (double)s0 + (double)s1;
        }
        sm.b.lg[p][j] = (float)acc;
    }
    __syncthreads();

    // rect splits: one thread per point (fp32, matching reference formula)
    if (tid < K1_PTS) {
        int gp = p0 + tid;
        float rat[7];
        #pragma unroll
        for (int i = 0; i < 7; i++)
            rat[i] = 1.f / (1.f + expf(-(sm.b.lg[tid][i] + br[i])));
        float R0[4];
        #pragma unroll
        for (int i = 0; i < 4; i++) R0[i] = r[gp*4 + i];

        float A[2][4], Bv[4][4], Cv[8][4];
        {
            float mid = R0[0]*(1.f-rat[0]) + R0[2]*rat[0];
            A[0][0]=R0[0]; A[0][1]=R0[1]; A[0][2]=mid;   A[0][3]=R0[3];
            A[1][0]=mid;   A[1][1]=R0[1]; A[1][2]=R0[2]; A[1][3]=R0[3];
        }
        #pragma unroll
        for (int k = 0; k < 2; k++) {
            float rt  = rat[1+k];
            float mid = A[k][1]*(1.f-rt) + A[k][3]*rt;
            Bv[k][0]=A[k][0];   Bv[k][1]=A[k][1]; Bv[k][2]=A[k][2];   Bv[k][3]=mid;
            Bv[2+k][0]=A[k][0]; Bv[2+k][1]=mid;   Bv[2+k][2]=A[k][2]; Bv[2+k][3]=A[k][3];
        }
        #pragma unroll
        for (int k = 0; k < 4; k++) {
            float rt  = rat[3+k];
            float mid = Bv[k][0]*(1.f-rt) + Bv[k][2]*rt;
            Cv[k][0]=Bv[k][0]; Cv[k][1]=Bv[k][1]; Cv[k][2]=mid;      Cv[k][3]=Bv[k][3];
            Cv[4+k][0]=mid;    Cv[4+k][1]=Bv[k][1]; Cv[4+k][2]=Bv[k][2]; Cv[4+k][3]=Bv[k][3];
        }
        #pragma unroll
        for (int i = 0; i < 8;  i++) sm.b.rects[tid][i]    = A[i>>2][i&3];
        #pragma unroll
        for (int i = 0; i < 16; i++) sm.b.rects[tid][8+i]  = Bv[i>>2][i&3];
        #pragma unroll
        for (int i = 0; i < 32; i++) sm.b.rects[tid][24+i] = Cv[i>>2][i&3];
    }
    __syncthreads();

    // softmax over rects per (point, group)
    if (tid < K1_PTS*8) {
        int p = tid >> 3, g = tid & 7;
        float m[8], mx = -1e30f;
        #pragma unroll
        for (int s = 0; s < 8; s++) { m[s] = sm.b.lg[p][7 + s*8 + g] + bm[s*8 + g]; mx = fmaxf(mx, m[s]); }
        float sum = 0.f;
        #pragma unroll
        for (int s = 0; s < 8; s++) { m[s] = expf(m[s]-mx); sum += m[s]; }
        float inv = 1.f / sum;
        #pragma unroll
        for (int s = 0; s < 8; s++) g_mask[(p0+p)*64 + s*8 + g] = m[s]*inv;
    }

    for (int i = tid; i < K1_PTS*8;  i += 256) out[L0OFF + p0*8  + i] = sm.b.rects[i>>3][i&7];
    for (int i = tid; i < K1_PTS*16; i += 256) out[L1OFF + p0*16 + i] = sm.b.rects[i>>4][8  + (i&15)];
    for (int i = tid; i < K1_PTS*32; i += 256) out[L2OFF + p0*32 + i] = sm.b.rects[i>>5][24 + (i&31)];
}

// ============================================================================
// K2: integral-image sampling, 18-corner dedup, edge terms dropped.
//     mask*inva folded into per-corner weight table w[i][g] (precomputed in
//     smem): corner loop accumulates DIRECTLY into zacc[8] — no Sraw regs.
//     float4 channels: 1 warp per point, 4 points per 128-thread block.
// ============================================================================
__global__ void __launch_bounds__(128) k2_sample(const float* __restrict__ out) {
    __shared__ float rrs[4][32];
    __shared__ float msk[4][64];
    __shared__ float sinva[4][8];
    __shared__ float wtab[4][18][8];
    __shared__ int   sxX[4][7], sxXm[4][7], syY[4][4], syYm[4][4];
    __shared__ float swx1[4][7], swx2[4][7], swy1[4][4], swy2[4][4];
    int tid = threadIdx.x;
    int w = tid >> 5, l = tid & 31;          // warp = point, lane = channel/4
    int pt = blockIdx.x*4 + w;

    rrs[w][l]     = out[L2OFF + pt*32 + l] * 95.f;
    msk[w][l]     = g_mask[pt*64 + l];
    msk[w][l+32]  = g_mask[pt*64 + 32 + l];
    __syncwarp();
    if (l < 7) {
        const int xsrc[7] = {0, 4, 22, 2, 6, 10, 14};
        float px = rrs[w][xsrc[l]];
        float Xf = ceilf(px);
        int X = (int)Xf, Xm = max(X-1, 0);
        float dx = Xf - px;
        float w1 = 0.5f*dx*dx;
        swx1[w][l] = w1; swx2[w][l] = dx - w1;
        sxX[w][l]  = X *(WIW*32);            // float4 units
        sxXm[w][l] = Xm*(WIW*32);
    } else if (l >= 8 && l < 12) {
        const int ysrc[4] = {1, 3, 7, 11};
        int t = l - 8;
        float py = rrs[w][ysrc[t]];
        float Yf = ceilf(py);
        int Y = (int)Yf, Ym = max(Y-1, 0);
        float dy = Yf - py;
        float w1 = 0.5f*dy*dy;
        swy1[w][t] = w1; swy2[w][t] = dy - w1;
        syY[w][t]  = Y *32;                  // float4 units
        syYm[w][t] = Ym*32;
    } else if (l >= 16 && l < 24) {
        int s = l - 16;
        float x1 = rrs[w][s*4+0], y1 = rrs[w][s*4+1];
        float x2 = rrs[w][s*4+2], y2 = rrs[w][s*4+3];
        sinva[w][s] = 1.f / (fabsf((x1-x2)*(y1-y2)) + 1e-9f);
    }
    __syncwarp();

    // per-corner scatter tables (corner i feeds rects U0 (sign G0) and U1 (G1))
    const int   CXI[18] = {0,0,1,1,3,3, 1,2,2,4,4, 0,1,5,5, 2,6,6};
    const int   CYI[18] = {0,1,0,1,0,1, 2,0,2,0,2, 3,3,1,3, 3,2,3};
    const int   U0 [18] = {0,0,1,4,0,0, 1,5,5,1,1, 2,6,2,2, 7,3,3};
    const float G0 [18] = {+1.f,-1.f,+1.f,+1.f,-1.f,+1.f, -1.f,-1.f,+1.f,-1.f,+1.f,
                           -1.f,+1.f,-1.f,+1.f, +1.f,-1.f,+1.f};
    const int   U1 [18] = {0,2,4,6,4,4, 3,0,7,5,5, 0,3,6,6, 0,7,7};
    const float G1 [18] = {0.f,+1.f,-1.f,-1.f,+1.f,-1.f, +1.f,0.f,-1.f,+1.f,-1.f,
                           0.f,-1.f,+1.f,-1.f, 0.f,+1.f,-1.f};

    // weight table: w[i][g] = G0*inva[U0]*msk[U0*8+g] + G1*inva[U1]*msk[U1*8+g]
    if (l < 18) {
        float c0 = G0[l]*sinva[w][U0[l]];
        float c1 = G1[l]*sinva[w][U1[l]];
        const float* m0 = &msk[w][U0[l]*8];
        const float* m1 = &msk[w][U1[l]*8];
        #pragma unroll
        for (int g = 0; g < 8; g++)
            wtab[w][l][g] = c0*m0[g] + c1*m1[g];
    }
    __syncwarp();

    const float4* TI4  = (const float4*)g_TI;
    const float4* TIT4 = (const float4*)g_TIT;
    const float4* TJX4 = (const float4*)g_TJX;
    const float4* TJY4 = (const float4*)g_TJY;
    int b = pt >> 11;
    int base4 = b*(HH*WIW*32) + l;           // float4 units; channels 4l..4l+3

    float4 zacc[8];
    #pragma unroll
    for (int g = 0; g < 8; g++) zacc[g] = make_float4(0.f,0.f,0.f,0.f);

    #pragma unroll
    for (int i = 0; i < 18; i++) {
        int xi = CXI[i], yi = CYI[i];
        int oX = sxX[w][xi], oXm = sxXm[w][xi];
        int oY = syY[w][yi], oYm = syYm[w][yi];
        float wx1 = swx1[w][xi], wx2 = swx2[w][xi];
        float wy1 = swy1[w][yi], wy2 = swy2[w][yi];
        int aXY   = base4 + oX  + oY;
        int aXYm  = base4 + oX  + oYm;
        int aXmY  = base4 + oXm + oY;
        int aXmYm = base4 + oXm + oYm;
        float4 tit  = TIT4[aXY];
        float4 jxm  = TJX4[aXYm], jx0 = TJX4[aXY];
        float4 jym  = TJY4[aXmY], jy0 = TJY4[aXY];
        float4 timm = TI4[aXmYm], tim0 = TI4[aXmY];
        float4 ti0m = TI4[aXYm],  ti00 = TI4[aXY];
        float4 v;
        v.x = tit.x - (wy1*jxm.x + wy2*jx0.x) - (wx1*jym.x + wx2*jy0.x)
            + (wx1*(wy1*timm.x + wy2*tim0.x) + wx2*(wy1*ti0m.x + wy2*ti00.x));
        v.y = tit.y - (wy1*jxm.y + wy2*jx0.y) - (wx1*jym.y + wx2*jy0.y)
            + (wx1*(wy1*timm.y + wy2*tim0.y) + wx2*(wy1*ti0m.y + wy2*ti00.y));
        v.z = tit.z - (wy1*jxm.z + wy2*jx0.z) - (wx1*jym.z + wx2*jy0.z)
            + (wx1*(wy1*timm.z + wy2*tim0.z) + wx2*(wy1*ti0m.z + wy2*ti00.z));
        v.w = tit.w - (wy1*jxm.w + wy2*jx0.w) - (wx1*jym.w + wx2*jy0.w)
            + (wx1*(wy1*timm.w + wy2*tim0.w) + wx2*(wy1*ti0m.w + wy2*ti00.w));
        #pragma unroll
        for (int g = 0; g < 8; g++) {
            float wv = wtab[w][i][g];
            zacc[g].x += wv*v.x; zacc[g].y += wv*v.y;
            zacc[g].z += wv*v.z; zacc[g].w += wv*v.w;
        }
    }

    float4* gZ4 = (float4*)g_Z;
    #pragma unroll
    for (int g = 0; g < 8; g++)
        gZ4[(pt*8 + g)*32 + l] = zacc[g];
}

// ============================================================================
// K3: per-group GEMM, 64 pts x 64 cols per block, 256 threads, 4x4 per thread
//     (R10-measured 67.8us configuration: Zs transposed [kk][p], pad 68)
// ============================================================================
__global__ void k3_gemm(const float* __restrict__ Wsamp, const float* __restrict__ bsamp,
                        float* __restrict__ out) {
    __shared__ float Zs[64][68];
    __shared__ float Wt[64][68];
    int p0  = blockIdx.x * 64;
    int g   = blockIdx.y;
    int tid = threadIdx.x;
    int tx  = tid & 15, ty = tid >> 4;
    float acc[4][4] = {};
    for (int kb = 0; kb < CIN; kb += 64) {
        __syncthreads();
        for (int i = tid; i < 4096; i += 256) {
            int p = i >> 6, kk = i & 63;
            Zs[kk][p] = g_Z[((p0+p)*8 + g)*CIN + kb + kk];
        }
        for (int i = tid; i < 4096; i += 256) {
            int kk = i >> 6, cc = i & 63;
            Wt[kk][cc] = Wsamp[(kb+kk)*CC + g*64 + cc];
        }
        __syncthreads();
        #pragma unroll 8
        for (int kk = 0; kk < 64; kk++) {
            float4 av = *(const float4*)&Zs[kk][ty*4];
            float4 bv = *(const float4*)&Wt[kk][tx*4];
            acc[0][0] += av.x*bv.x; acc[0][1] += av.x*bv.y; acc[0][2] += av.x*bv.z; acc[0][3] += av.x*bv.w;
            acc[1][0] += av.y*bv.x; acc[1][1] += av.y*bv.y; acc[1][2] += av.y*bv.z; acc[1][3] += av.y*bv.w;
            acc[2][0] += av.z*bv.x; acc[2][1] += av.z*bv.y; acc[2][2] += av.z*bv.z; acc[2][3] += av.z*bv.w;
            acc[3][0] += av.w*bv.x; acc[3][1] += av.w*bv.y; acc[3][2] += av.w*bv.z; acc[3][3] += av.w*bv.w;
        }
    }
    int c0 = g*64 + tx*4;
    float4 bb = *(const float4*)&bsamp[c0];
    #pragma unroll
    for (int i = 0; i < 4; i++) {
        int row = p0 + ty*4 + i;
        float4 o;
        o.x = acc[i][0] + bb.x; o.y = acc[i][1] + bb.y;
        o.z = acc[i][2] + bb.z; o.w = acc[i][3] + bb.w;
        *(float4*)&out[row*CC + c0] = o;
    }
}

// ============================================================================
// K4: LayerNorm + residual, in place. Two-pass variance; float4 I/O.
// ============================================================================
__global__ void k4_ln(const float* __restrict__ x, const float* __restrict__ lng,
                      const float* __restrict__ lnb, float* __restrict__ out) {
    __shared__ float red[4];
    int pt = blockIdx.x, tid = threadIdx.x;
    int c = tid*4;
    float4 v = *(const float4*)&out[pt*CC + c];
    float s1 = (v.x+v.y) + (v.z+v.w);
    #pragma unroll
    for (int o = 16; o; o >>= 1) s1 += __shfl_xor_sync(0xFFFFFFFFu, s1, o);
    if ((tid & 31) == 0) red[tid>>5] = s1;
    __syncthreads();
    float mu = (red[0]+red[1]+red[2]+red[3]) * (1.f/512.f);
    __syncthreads();

    float d0 = v.x-mu, d1 = v.y-mu, d2 = v.z-mu, d3 = v.w-mu;
    float s2 = (d0*d0+d1*d1) + (d2*d2+d3*d3);
    #pragma unroll
    for (int o = 16; o; o >>= 1) s2 += __shfl_xor_sync(0xFFFFFFFFu, s2, o);
    if ((tid & 31) == 0) red[tid>>5] = s2;
    __syncthreads();
    float var = (red[0]+red[1]+red[2]+red[3]) * (1.f/512.f);
    float rs  = rsqrtf(var + 1e-5f);

    float4 gv = *(const float4*)&lng[c];
    float4 bv = *(const float4*)&lnb[c];
    float4 xv = *(const float4*)&x[pt*CC + c];
    float4 o;
    o.x = d0*rs*gv.x + bv.x + xv.x;
    o.y = d1*rs*gv.y + bv.y + xv.y;
    o.z = d2*rs*gv.z + bv.z + xv.z;
    o.w = d3*rs*gv.w + bv.w + xv.w;
    *(float4*)&out[pt*CC + c] = o;
}

// ============================================================================
extern "C" void kernel_launch(void* const* d_in, const int* in_sizes, int n_in,
                              void* d_out, int out_size) {
    const float* x  = (const float*)d_in[0];
    const float* r  = (const float*)d_in[1];
    const float* I  = (const float*)d_in[2];
    const float* IX = (const float*)d_in[3];
    const float* IY = (const float*)d_in[4];
    const float* IT = (const float*)d_in[5];
    const float* Wr = (const float*)d_in[6];
    const float* br = (const float*)d_in[7];
    const float* Wm = (const float*)d_in[8];
    const float* bm = (const float*)d_in[9];
    const float* Ws = (const float*)d_in[10];
    const float* bs = (const float*)d_in[11];
    const float* lg = (const float*)d_in[12];
    const float* lb = (const float*)d_in[13];
    float* out = (float*)d_out;

    k01_fused<<<K01_BLOCKS, 256>>>(I, IX, IY, IT, x, r, Wr, br, Wm, bm, out);
    k2_sample<<<NPTS/4, 128>>>(out);
    k3_gemm<<<dim3(NPTS/64, 8), 256>>>(Ws, bs, out);
    k4_ln<<<NPTS, 128>>>(x, lg, lb, out);
}